// round 4
// baseline (speedup 1.0000x reference)
#include <cuda_runtime.h>
#include <math.h>

#define R 1024
#define B 16
#define D 1024
#define K_ACTIVE 20
#define FB_DECAY 0.9f
#define REFR_W 1.0f
#define FB_W 0.5f

#define NBLK 2048          // score blocks (8 rows each)
#define NMS_FIRST (NBLK - B)

__device__ int g_count = 0;   // blocks finished with score phase
__device__ int g_done  = 0;   // NMS blocks finished (for counter reset)

// ordered-uint transform: max(ord(f)) <=> max(f)
__device__ __forceinline__ unsigned f2ord(float f) {
    unsigned u = __float_as_uint(f);
    return u ^ (((int)u >> 31) | 0x80000000u);
}

__global__ void __launch_bounds__(256)
fused_kernel(const float4* __restrict__ H,
             const float4* __restrict__ M,
             const float4* __restrict__ w,
             const float*  __restrict__ theta,
             const float*  __restrict__ refr,
             const float*  __restrict__ fb,
             float* __restrict__ adj_out,     // [B,R]
             float* __restrict__ hard_out,    // [B,R]
             float4* __restrict__ hs_out)     // [R,B,D]
{
    const int t    = threadIdx.x;
    const int lane = t & 31;
    const int warp = t >> 5;

    // ---------------- Phase 1: score + zero (one warp per row) -------------
    {
        int gw = blockIdx.x * 8 + warp;          // row id rb in [0, R*B)
        int r = gw >> 4;
        int b = gw & 15;

        const float4* hrow = H + (size_t)gw * (D / 4);
        const float4* mrow = M + (size_t)gw * (D / 4);
        float4*       orow = hs_out + (size_t)gw * (D / 4);
        const float4 z4 = make_float4(0.f, 0.f, 0.f, 0.f);

        float dot = 0.f, ss = 0.f;
#pragma unroll
        for (int i = 0; i < (D / 4) / 32; i++) {
            int j = i * 32 + lane;
            float4 hv = hrow[j];
            float4 wv = w[j];
            float4 mv = mrow[j];
            dot += hv.x * wv.x + hv.y * wv.y + hv.z * wv.z + hv.w * wv.w;
            ss  += mv.x * mv.x + mv.y * mv.y + mv.z * mv.z + mv.w * mv.w;
            orow[j] = z4;
        }
#pragma unroll
        for (int o = 16; o > 0; o >>= 1) {
            dot += __shfl_down_sync(0xffffffffu, dot, o);
            ss  += __shfl_down_sync(0xffffffffu, ss,  o);
        }
        if (lane == 0) {
            int br = b * R + r;
            float fb_new = FB_DECAY * fb[br] + (1.0f - FB_DECAY) * sqrtf(ss);
            adj_out[br] = dot - theta[r] - REFR_W * refr[br] - FB_W * fb_new;
        }
    }

    // ---------------- Release: fence + ticket ------------------------------
    __shared__ int s_tick;
    __threadfence();
    __syncthreads();
    if (t == 0) s_tick = atomicAdd(&g_count, 1);
    __syncthreads();
    int tick = s_tick;
    if (tick < NMS_FIRST) return;            // not a designated NMS block

    const int b = tick - NMS_FIRST;          // this block owns batch b

    // wait until every block's adj writes are visible
    if (t == 0) {
        while (*(volatile int*)&g_count < NBLK) { }
    }
    __syncthreads();
    __threadfence();

    // ---------------- Phase 2: NMS for batch b -----------------------------
    __shared__ unsigned long long ks[R];     // packed keys
    __shared__ float hm[R];                  // hard mask
    __shared__ int   sel[K_ACTIVE];

    for (int i = t; i < R; i += 256) {
        float v = adj_out[b * R + i];
        ks[i] = ((unsigned long long)f2ord(v) << 32) | (unsigned)(~i);
        hm[i] = 0.f;
    }
    __syncthreads();

    if (warp == 0) {
        for (int it = 0; it < K_ACTIVE; it++) {
            // lane-local running max over owned slots (4 accumulators)
            unsigned long long a0 = 0, a1 = 0, a2 = 0, a3 = 0;
#pragma unroll
            for (int j = 0; j < 8; j++) {
                unsigned long long k0 = ks[(4 * j + 0) * 32 + lane];
                unsigned long long k1 = ks[(4 * j + 1) * 32 + lane];
                unsigned long long k2 = ks[(4 * j + 2) * 32 + lane];
                unsigned long long k3 = ks[(4 * j + 3) * 32 + lane];
                a0 = max(a0, k0); a1 = max(a1, k1);
                a2 = max(a2, k2); a3 = max(a3, k3);
            }
            unsigned long long m = max(max(a0, a1), max(a2, a3));
            // warp butterfly max (all lanes get winner)
#pragma unroll
            for (int o = 16; o > 0; o >>= 1) {
                unsigned long long om = __shfl_xor_sync(0xffffffffu, m, o);
                m = max(m, om);
            }
            int s = (int)(~(unsigned)m) & (R - 1);   // decode region index

            if (lane == 0) { sel[it] = s; hm[s] = 1.f; }
            // lanes 0..6 suppress s and its 6 hex neighbors (32x32 torus)
            if (lane < 7) {
                int rr = s >> 5, cc = s & 31;
                int tgt;
                switch (lane) {
                    case 0: tgt = s; break;
                    case 1: tgt = (rr << 5) | ((cc - 1) & 31); break;
                    case 2: tgt = (rr << 5) | ((cc + 1) & 31); break;
                    case 3: tgt = (((rr - 1) & 31) << 5) | cc; break;
                    case 4: tgt = (((rr + 1) & 31) << 5) | cc; break;
                    case 5: tgt = (((rr - 1) & 31) << 5) | ((cc + 1) & 31); break;
                    default: tgt = (((rr + 1) & 31) << 5) | ((cc - 1) & 31); break;
                }
                ks[tgt] = 0ull;
            }
            __syncwarp();
        }
    }
    __syncthreads();

    // write hard[b,:]
    for (int i = t; i < R; i += 256)
        hard_out[b * R + i] = hm[i];

    // ---------------- Phase 3: scatter-copy active rows --------------------
    // ste = hard + sigmoid - stopgrad(sigmoid): numerically hard (err<6e-8).
#pragma unroll 4
    for (int s = 0; s < K_ACTIVE; s++) {
        int r = sel[s];
        size_t row = (size_t)(r * B + b) * (D / 4);
        hs_out[row + t] = H[row + t];
    }

    // ---------------- Reset counters for next graph replay -----------------
    __threadfence();
    __syncthreads();
    if (t == 0) {
        int d = atomicAdd(&g_done, 1);
        if (d == B - 1) {                 // last NMS block resets everything
            atomicExch(&g_count, 0);
            atomicExch(&g_done, 0);
            __threadfence();
        }
    }
}

// ---------------------------------------------------------------------------
extern "C" void kernel_launch(void* const* d_in, const int* in_sizes, int n_in,
                              void* d_out, int out_size)
{
    const float* H     = (const float*)d_in[0];   // [R,B,D]
    const float* M     = (const float*)d_in[1];   // [R,B,D]
    const float* w     = (const float*)d_in[2];   // [D]
    const float* theta = (const float*)d_in[3];   // [R]
    const float* refr  = (const float*)d_in[4];   // [B,R]
    const float* fb    = (const float*)d_in[5];   // [B,R]
    // d_in[6] = neighbor_indices: fixed 32x32 toroidal hex grid, computed
    // arithmetically in-kernel.

    float* out  = (float*)d_out;
    float* Hs   = out;                              // [R,B,D]
    float* hard = out + (size_t)R * B * D;          // [B,R]
    float* adj  = hard + (size_t)B * R;             // [B,R]

    fused_kernel<<<NBLK, 256>>>((const float4*)H, (const float4*)M,
                                (const float4*)w, theta, refr, fb,
                                adj, hard, (float4*)Hs);
}

// round 5
// speedup vs baseline: 1.2205x; 1.2205x over previous
#include <cuda_runtime.h>
#include <math.h>

#define R 1024
#define B 16
#define D 1024
#define K_ACTIVE 20
#define FB_DECAY 0.9f
#define REFR_W 1.0f
#define FB_W 0.5f

// ---------------------------------------------------------------------------
// Kernel 1: fused per-(r,b) row reductions + zero-fill of the Hs output row.
//   adj[b,r] = dot(H,w) - theta[r] - refr[b,r] - 0.5*(0.9*fb + 0.1*||msg||)
//   Hs[r,b,:] = 0   (active rows overwritten by the nms_scatter kernel)
// One warp per row; streaming float4 traffic; w staged in smem.
// ---------------------------------------------------------------------------
__global__ void __launch_bounds__(256)
score_zero_kernel(const float4* __restrict__ H,
                  const float4* __restrict__ M,
                  const float4* __restrict__ w,
                  const float*  __restrict__ theta,
                  const float*  __restrict__ refr,
                  const float*  __restrict__ fb,
                  float* __restrict__ adj_out,
                  float4* __restrict__ hs_out)
{
    __shared__ float4 s_w[D / 4];
    s_w[threadIdx.x] = w[threadIdx.x];
    __syncthreads();

    int gw   = blockIdx.x * 8 + (threadIdx.x >> 5);   // row id rb
    int lane = threadIdx.x & 31;
    int r = gw >> 4;
    int b = gw & 15;

    const float4* hrow = H + (size_t)gw * (D / 4);
    const float4* mrow = M + (size_t)gw * (D / 4);
    float4*       orow = hs_out + (size_t)gw * (D / 4);
    const float4 z4 = make_float4(0.f, 0.f, 0.f, 0.f);

    float dot = 0.f, ss = 0.f;
#pragma unroll
    for (int i = 0; i < (D / 4) / 32; i++) {
        int j = i * 32 + lane;
        float4 hv = __ldcs(&hrow[j]);
        float4 mv = __ldcs(&mrow[j]);
        float4 wv = s_w[j];
        dot += hv.x * wv.x + hv.y * wv.y + hv.z * wv.z + hv.w * wv.w;
        ss  += mv.x * mv.x + mv.y * mv.y + mv.z * mv.z + mv.w * mv.w;
        __stcs(&orow[j], z4);
    }
#pragma unroll
    for (int o = 16; o > 0; o >>= 1) {
        dot += __shfl_down_sync(0xffffffffu, dot, o);
        ss  += __shfl_down_sync(0xffffffffu, ss,  o);
    }
    if (lane == 0) {
        int br = b * R + r;
        float fb_new = FB_DECAY * fb[br] + (1.0f - FB_DECAY) * sqrtf(ss);
        adj_out[br] = dot - theta[r] - REFR_W * refr[br] - FB_W * fb_new;
    }
}

// ordered-uint transform: max(ord(f)) <=> max(f)
__device__ __forceinline__ unsigned f2ord(float f) {
    unsigned u = __float_as_uint(f);
    return u ^ (((int)u >> 31) | 0x80000000u);
}

// ---------------------------------------------------------------------------
// Kernel 2: per-batch greedy hex NMS (warp 0, packed 64-bit keys) + hard
// write + scatter-copy of the 20 active rows. One block per batch.
// Key = (ord(score) << 32) | ~idx  -> single max-reduction gives the
// JAX-stable winner (ties -> smaller region index).
// Hex neighbors computed arithmetically (32x32 torus).
// ---------------------------------------------------------------------------
__global__ void __launch_bounds__(256)
nms_scatter_kernel(const float* __restrict__ adj,
                   const float4* __restrict__ H,
                   float* __restrict__ hard,
                   float4* __restrict__ hs_out)
{
    const int b    = blockIdx.x;
    const int t    = threadIdx.x;
    const int lane = t & 31;
    const int warp = t >> 5;

    __shared__ unsigned long long ks[R];
    __shared__ float hm[R];
    __shared__ int   sel[K_ACTIVE];

    for (int i = t; i < R; i += 256) {
        float v = adj[b * R + i];
        ks[i] = ((unsigned long long)f2ord(v) << 32) | (unsigned)(~i);
        hm[i] = 0.f;
    }
    __syncthreads();

    if (warp == 0) {
        for (int it = 0; it < K_ACTIVE; it++) {
            unsigned long long a0 = 0, a1 = 0, a2 = 0, a3 = 0;
#pragma unroll
            for (int j = 0; j < 8; j++) {
                a0 = max(a0, ks[(4 * j + 0) * 32 + lane]);
                a1 = max(a1, ks[(4 * j + 1) * 32 + lane]);
                a2 = max(a2, ks[(4 * j + 2) * 32 + lane]);
                a3 = max(a3, ks[(4 * j + 3) * 32 + lane]);
            }
            unsigned long long m = max(max(a0, a1), max(a2, a3));
#pragma unroll
            for (int o = 16; o > 0; o >>= 1) {
                unsigned long long om = __shfl_xor_sync(0xffffffffu, m, o);
                m = max(m, om);
            }
            int s = (int)(~(unsigned)m) & (R - 1);

            if (lane == 0) { sel[it] = s; hm[s] = 1.f; }
            if (lane < 7) {
                int rr = s >> 5, cc = s & 31;
                int tgt;
                switch (lane) {
                    case 0: tgt = s; break;
                    case 1: tgt = (rr << 5) | ((cc - 1) & 31); break;
                    case 2: tgt = (rr << 5) | ((cc + 1) & 31); break;
                    case 3: tgt = (((rr - 1) & 31) << 5) | cc; break;
                    case 4: tgt = (((rr + 1) & 31) << 5) | cc; break;
                    case 5: tgt = (((rr - 1) & 31) << 5) | ((cc + 1) & 31); break;
                    default: tgt = (((rr + 1) & 31) << 5) | ((cc - 1) & 31); break;
                }
                ks[tgt] = 0ull;
            }
            __syncwarp();
        }
    }
    __syncthreads();

    // hard[b,:]  (1024 floats = 256 float4, one per thread)
    ((float4*)(hard + b * R))[t] = ((const float4*)hm)[t];

    // scatter-copy the 20 active rows: Hs[r,b,:] = H[r,b,:]
    // (ste = hard + sigma - stopgrad(sigma): numerically hard, err < 6e-8)
#pragma unroll
    for (int s = 0; s < K_ACTIVE; s++) {
        int r = sel[s];
        size_t row = (size_t)(r * B + b) * (D / 4);
        hs_out[row + t] = H[row + t];
    }
}

// ---------------------------------------------------------------------------
extern "C" void kernel_launch(void* const* d_in, const int* in_sizes, int n_in,
                              void* d_out, int out_size)
{
    const float* H     = (const float*)d_in[0];   // [R,B,D]
    const float* M     = (const float*)d_in[1];   // [R,B,D]
    const float* w     = (const float*)d_in[2];   // [D]
    const float* theta = (const float*)d_in[3];   // [R]
    const float* refr  = (const float*)d_in[4];   // [B,R]
    const float* fb    = (const float*)d_in[5];   // [B,R]
    // d_in[6] = neighbor_indices: fixed 32x32 toroidal hex grid, computed
    // arithmetically in-kernel.

    float* out  = (float*)d_out;
    float* Hs   = out;                              // [R,B,D]
    float* hard = out + (size_t)R * B * D;          // [B,R]
    float* adj  = hard + (size_t)B * R;             // [B,R]

    score_zero_kernel<<<(R * B) / 8, 256>>>((const float4*)H, (const float4*)M,
                                            (const float4*)w, theta, refr, fb,
                                            adj, (float4*)Hs);
    nms_scatter_kernel<<<B, 256>>>(adj, (const float4*)H, hard, (float4*)Hs);
}

// round 6
// speedup vs baseline: 1.2518x; 1.0256x over previous
#include <cuda_runtime.h>
#include <math.h>

#define R 1024
#define B 16
#define D 1024
#define K_ACTIVE 20
#define FB_DECAY 0.9f
#define REFR_W 1.0f
#define FB_W 0.5f

// ---------------------------------------------------------------------------
// Kernel 1: fused per-(r,b) row reductions + zero-fill of the Hs output row.
//   adj[b,r] = dot(H,w) - theta[r] - refr[b,r] - 0.5*(0.9*fb + 0.1*||msg||)
//   Hs[r,b,:] = 0   (active rows overwritten by the nms_scatter kernel)
// ---------------------------------------------------------------------------
__global__ void __launch_bounds__(256)
score_zero_kernel(const float4* __restrict__ H,
                  const float4* __restrict__ M,
                  const float4* __restrict__ w,
                  const float*  __restrict__ theta,
                  const float*  __restrict__ refr,
                  const float*  __restrict__ fb,
                  float* __restrict__ adj_out,
                  float4* __restrict__ hs_out)
{
    __shared__ float4 s_w[D / 4];
    s_w[threadIdx.x] = w[threadIdx.x];
    __syncthreads();

    int gw   = blockIdx.x * 8 + (threadIdx.x >> 5);   // row id rb
    int lane = threadIdx.x & 31;
    int r = gw >> 4;
    int b = gw & 15;

    const float4* hrow = H + (size_t)gw * (D / 4);
    const float4* mrow = M + (size_t)gw * (D / 4);
    float4*       orow = hs_out + (size_t)gw * (D / 4);
    const float4 z4 = make_float4(0.f, 0.f, 0.f, 0.f);

    float dot = 0.f, ss = 0.f;
#pragma unroll
    for (int i = 0; i < (D / 4) / 32; i++) {
        int j = i * 32 + lane;
        float4 hv = __ldcs(&hrow[j]);
        float4 mv = __ldcs(&mrow[j]);
        float4 wv = s_w[j];
        dot += hv.x * wv.x + hv.y * wv.y + hv.z * wv.z + hv.w * wv.w;
        ss  += mv.x * mv.x + mv.y * mv.y + mv.z * mv.z + mv.w * mv.w;
        __stcs(&orow[j], z4);
    }
#pragma unroll
    for (int o = 16; o > 0; o >>= 1) {
        dot += __shfl_down_sync(0xffffffffu, dot, o);
        ss  += __shfl_down_sync(0xffffffffu, ss,  o);
    }
    if (lane == 0) {
        int br = b * R + r;
        float fb_new = FB_DECAY * fb[br] + (1.0f - FB_DECAY) * sqrtf(ss);
        adj_out[br] = dot - theta[r] - REFR_W * refr[br] - FB_W * fb_new;
    }
}

// ordered-uint transform: max(ord(f)) <=> max(f)
__device__ __forceinline__ unsigned f2ord(float f) {
    unsigned u = __float_as_uint(f);
    return u ^ (((int)u >> 31) | 0x80000000u);
}

__device__ __forceinline__ unsigned long long row_max(
    const unsigned long long* __restrict__ my)
{
    const ulonglong2* m2 = (const ulonglong2*)my;
    unsigned long long a = 0, b = 0;
#pragma unroll
    for (int j = 0; j < 8; j++) {
        ulonglong2 x = m2[2 * j];
        ulonglong2 y = m2[2 * j + 1];
        a = max(a, max(x.x, x.y));
        b = max(b, max(y.x, y.y));
    }
    return max(a, b);
}

// ---------------------------------------------------------------------------
// Kernel 2: per-batch greedy hex NMS + hard write + scatter-copy.
// Warp 0 does NMS with an incremental hierarchical argmax:
//   - lane l owns grid row l (32 contiguous entries), keeps its max in a reg
//   - key = (ord(score) << 32) | ~idx  -> max key == JAX-stable winner
//   - warp reduction = 2x REDUX (__reduce_max_sync) instead of u64 butterfly
//   - suppression hits only rows {rr-1, rr, rr+1} -> 3 lanes re-scan
// Hex neighbors computed arithmetically (32x32 torus).
// ---------------------------------------------------------------------------
__global__ void __launch_bounds__(256)
nms_scatter_kernel(const float* __restrict__ adj,
                   const float4* __restrict__ H,
                   float* __restrict__ hard,
                   float4* __restrict__ hs_out)
{
    const int b    = blockIdx.x;
    const int t    = threadIdx.x;
    const int lane = t & 31;
    const int warp = t >> 5;

    __shared__ unsigned long long ks[R];
    __shared__ float hm[R];
    __shared__ int   sel[K_ACTIVE];

    for (int i = t; i < R; i += 256) {
        float v = adj[b * R + i];
        ks[i] = ((unsigned long long)f2ord(v) << 32) | (unsigned)(~i);
        hm[i] = 0.f;
    }
    __syncthreads();

    if (warp == 0) {
        const unsigned long long* my = ks + lane * 32;   // lane owns grid row 'lane'
        unsigned long long best = row_max(my);

        for (int it = 0; it < K_ACTIVE; it++) {
            unsigned hi = (unsigned)(best >> 32);
            unsigned mx = __reduce_max_sync(0xffffffffu, hi);
            unsigned lo = (hi == mx) ? (unsigned)best : 0u;
            lo = __reduce_max_sync(0xffffffffu, lo);
            int s = (int)(~lo) & (R - 1);

            int rr = s >> 5, cc = s & 31;
            if (lane == 0) { sel[it] = s; hm[s] = 1.f; }
            // lanes 0..6 suppress s and its 6 hex neighbors (32x32 torus)
            if (lane < 7) {
                int tgt;
                switch (lane) {
                    case 0: tgt = s; break;
                    case 1: tgt = (rr << 5) | ((cc - 1) & 31); break;
                    case 2: tgt = (rr << 5) | ((cc + 1) & 31); break;
                    case 3: tgt = (((rr - 1) & 31) << 5) | cc; break;
                    case 4: tgt = (((rr + 1) & 31) << 5) | cc; break;
                    case 5: tgt = (((rr - 1) & 31) << 5) | ((cc + 1) & 31); break;
                    default: tgt = (((rr + 1) & 31) << 5) | ((cc - 1) & 31); break;
                }
                ks[tgt] = 0ull;
            }
            __syncwarp();
            // only the 3 affected rows re-scan
            int dl = (lane - rr) & 31;
            if (dl <= 1 || dl == 31)
                best = row_max(my);
        }
    }
    __syncthreads();

    // hard[b,:]  (1024 floats = 256 float4, one per thread)
    ((float4*)(hard + b * R))[t] = ((const float4*)hm)[t];

    // scatter-copy the 20 active rows: Hs[r,b,:] = H[r,b,:]
    // (ste = hard + sigma - stopgrad(sigma): numerically hard, err < 6e-8)
#pragma unroll
    for (int s = 0; s < K_ACTIVE; s++) {
        int r = sel[s];
        size_t row = (size_t)(r * B + b) * (D / 4);
        hs_out[row + t] = H[row + t];
    }
}

// ---------------------------------------------------------------------------
extern "C" void kernel_launch(void* const* d_in, const int* in_sizes, int n_in,
                              void* d_out, int out_size)
{
    const float* H     = (const float*)d_in[0];   // [R,B,D]
    const float* M     = (const float*)d_in[1];   // [R,B,D]
    const float* w     = (const float*)d_in[2];   // [D]
    const float* theta = (const float*)d_in[3];   // [R]
    const float* refr  = (const float*)d_in[4];   // [B,R]
    const float* fb    = (const float*)d_in[5];   // [B,R]
    // d_in[6] = neighbor_indices: fixed 32x32 toroidal hex grid, computed
    // arithmetically in-kernel.

    float* out  = (float*)d_out;
    float* Hs   = out;                              // [R,B,D]
    float* hard = out + (size_t)R * B * D;          // [B,R]
    float* adj  = hard + (size_t)B * R;             // [B,R]

    score_zero_kernel<<<(R * B) / 8, 256>>>((const float4*)H, (const float4*)M,
                                            (const float4*)w, theta, refr, fb,
                                            adj, (float4*)Hs);
    nms_scatter_kernel<<<B, 256>>>(adj, (const float4*)H, hard, (float4*)Hs);
}